// round 8
// baseline (speedup 1.0000x reference)
#include <cuda_runtime.h>
#include <cuda_fp16.h>
#include <cstdint>

// out[b,k] = sum_ij in1[b,i]*in2[b,j]*cb[k,ij]   (GEMM: out = P @ Bmat)
// mma.sync.m16n8k16 f16, exact 2-mma product per 8x8 block:
//   mma1: [ph|pl] x [bh|bh], mma2: [ph|pl] x [bl|bl]  => (ph+pl)(bh+bl) exact.
// Runtime 8x8 block-sparsity (11x11 blocks). Warp = (16-row group, nt-half):
// nt 0-5 -> even warps, nt 6-10 -> odd warps. 512 thr, 2 CTAs/SM, 50% occ.
// Stores: scalar STG.32 (324B rows -> odd rows only 4B-aligned), BOTH
// elements bounds-guarded against NKOUT (round-7 bug: unguarded first store).

#define NKOUT 81
#define NIJ   81
#define NT    11
#define KT    11
#define NBLK  (NT * KT)
#define TPB   512
#define ROWS  128
#define NTLO  6              // nt 0..5 -> half 0; nt 6..10 -> half 1

__device__ uint2    g_blk[NBLK * 32];
__device__ unsigned g_mask[KT];
__device__ int      g_nslot;

__global__ void prep_kernel(const float* __restrict__ cb) {
    __shared__ int      flag[NBLK];
    __shared__ int      slotof[NBLK];
    __shared__ unsigned smask[KT];
    const int tid = threadIdx.x;
    if (tid < KT) smask[tid] = 0;
    __syncthreads();

    const int kt = tid / NT;
    const int nt = tid % NT;
    if (tid < NBLK) {
        int f = 0;
        for (int q = 0; q < 8; q++)
            for (int n = 0; n < 8; n++) {
                int ij = kt * 8 + q, ko = nt * 8 + n;
                float v = (ij < NIJ && ko < NKOUT) ? cb[ko * NIJ + ij] : 0.f;
                if (v != 0.f) f = 1;
            }
        flag[tid] = f;
        if (f) atomicOr(&smask[kt], 1u << nt);
    }
    __syncthreads();
    if (tid == 0) {
        int s = 0;
        for (int b = 0; b < NBLK; b++) { slotof[b] = s; s += flag[b]; }
        g_nslot = s;
    }
    __syncthreads();
    if (tid < KT) g_mask[tid] = smask[tid];

    if (tid < NBLK && flag[tid]) {
        const int slot = slotof[tid];
        for (int L = 0; L < 32; L++) {
            int g = L >> 2, t = L & 3;        // b frag: {B[2t][g], B[2t+1][g]}
            int ko  = nt * 8 + g;
            int ij0 = kt * 8 + 2 * t, ij1 = ij0 + 1;
            float v0 = (ij0 < NIJ && ko < NKOUT) ? cb[ko * NIJ + ij0] : 0.f;
            float v1 = (ij1 < NIJ && ko < NKOUT) ? cb[ko * NIJ + ij1] : 0.f;
            __half h0 = __float2half_rn(v0);
            __half h1 = __float2half_rn(v1);
            __half l0 = __float2half_rn(v0 - __half2float(h0));
            __half l1 = __float2half_rn(v1 - __half2float(h1));
            __half2 bh = __halves2half2(h0, h1);
            __half2 bl = __halves2half2(l0, l1);
            uint2 u;
            u.x = *(unsigned*)&bh;
            u.y = *(unsigned*)&bl;
            g_blk[slot * 32 + L] = u;
        }
    }
}

__device__ __forceinline__ void mma16(float* d,
                                      unsigned a0, unsigned a1, unsigned a2, unsigned a3,
                                      unsigned b0, unsigned b1) {
    asm volatile(
        "mma.sync.aligned.m16n8k16.row.col.f32.f16.f16.f32 "
        "{%0,%1,%2,%3}, {%4,%5,%6,%7}, {%8,%9}, {%0,%1,%2,%3};"
        : "+f"(d[0]), "+f"(d[1]), "+f"(d[2]), "+f"(d[3])
        : "r"(a0), "r"(a1), "r"(a2), "r"(a3), "r"(b0), "r"(b1));
}

__device__ __forceinline__ unsigned pack2(float x, float y) {
    __half2 h = __halves2half2(__float2half_rn(x), __float2half_rn(y));
    return *(unsigned*)&h;
}

// shared (floats): in1s[1152] | in2s[1152] | mask[16] | sB (uint2, worst dense)
#define IN1_OFF  0
#define IN2_OFF  1152
#define MASK_OFF 2304
#define SB_OFF   2320                          // 2320*4 % 8 == 0
#define SMEM_FLOATS (SB_OFF + NBLK * 64)       // 2320 + 7744 = 10064 -> 40256 B

__global__ void __launch_bounds__(TPB, 2) tp_mma(
    const float* __restrict__ in1,
    const float* __restrict__ in2,
    float* __restrict__ out,
    int B)
{
    extern __shared__ float smem[];
    float*    in1s  = smem + IN1_OFF;
    float*    in2s  = smem + IN2_OFF;
    unsigned* smask = (unsigned*)(smem + MASK_OFF);
    uint2*    sB    = (uint2*)(smem + SB_OFF);

    const int tid  = threadIdx.x;
    const int base = blockIdx.x * ROWS;

    const int lim = B * 9 - base * 9;
    for (int idx = tid; idx < ROWS * 9; idx += TPB) {
        bool ok = idx < lim;
        in1s[idx] = ok ? in1[base * 9 + idx] : 0.f;
        in2s[idx] = ok ? in2[base * 9 + idx] : 0.f;
    }
    const int nslot = g_nslot;
    for (int idx = tid; idx < nslot * 32; idx += TPB) sB[idx] = g_blk[idx];
    if (tid < KT) smask[tid] = g_mask[tid];
    __syncthreads();

    const int lane = tid & 31;
    const int warp = tid >> 5;          // 0..15
    const int rg   = warp >> 1;         // row group 0..7
    const int h    = warp & 1;          // nt half
    const int g = lane >> 2;
    const int t = lane & 3;
    const int r0 = rg * 16 + g;
    const int r1 = r0 + 8;

    float acc[NTLO][4];
#pragma unroll
    for (int n = 0; n < NTLO; n++) {
        acc[n][0] = 0.f; acc[n][1] = 0.f; acc[n][2] = 0.f; acc[n][3] = 0.f;
    }

    const float* a0p = in1s + r0 * 9;
    const float* a1p = in1s + r1 * 9;
    const float* c0p = in2s + r0 * 9;
    const float* c1p = in2s + r1 * 9;

    int slot = 0;
#pragma unroll
    for (int kt = 0; kt < KT; kt++) {
        const int c0 = kt * 8 + 2 * t;
        const int c1 = c0 + 1;
        const int i0 = (c0 * 57) >> 9;  const int j0 = c0 - 9 * i0;
        const int i1 = (c1 * 57) >> 9;  const int j1 = c1 - 9 * i1;

        float p00 = a0p[i0] * c0p[j0];
        float p10 = a1p[i0] * c1p[j0];
        float p01 = a0p[i1] * c0p[j1];
        float p11 = a1p[i1] * c1p[j1];
        if (c0 >= NIJ) { p00 = 0.f; p10 = 0.f; }
        if (c1 >= NIJ) { p01 = 0.f; p11 = 0.f; }

        const unsigned ra0 = pack2(p00, p01);
        const unsigned ra1 = pack2(p10, p11);
        __half2 h0 = *(__half2*)&ra0;
        __half2 h1 = *(__half2*)&ra1;
        const unsigned ra2 = pack2(p00 - __low2float(h0), p01 - __high2float(h0));
        const unsigned ra3 = pack2(p10 - __low2float(h1), p11 - __high2float(h1));

        const unsigned m = smask[kt];
#pragma unroll
        for (int nt = 0; nt < NT; nt++) {
            if (m & (1u << nt)) {
                const int half = (nt >= NTLO) ? 1 : 0;       // compile-time
                if (half == h) {                             // uniform runtime
                    const int ai = (nt >= NTLO) ? nt - NTLO : nt;
                    uint2 bq = sB[slot * 32 + lane];
                    mma16(acc[ai], ra0, ra1, ra2, ra3, bq.x, bq.x);
                    mma16(acc[ai], ra0, ra1, ra2, ra3, bq.y, bq.y);
                }
                slot++;
            }
        }
    }

    // direct scalar stores, both elements bounds-guarded (c can reach 86 > 81)
    const int row0 = base + r0;
    const int row1 = base + r1;
    const bool ok0 = row0 < B;
    const bool ok1 = row1 < B;
    float* o0 = out + row0 * NKOUT;
    float* o1 = out + row1 * NKOUT;
    const int nmine = h ? (NT - NTLO) : NTLO;   // 5 or 6, uniform per warp
#pragma unroll
    for (int nt0 = 0; nt0 < NTLO; nt0++) {
        if (nt0 >= nmine) break;
        const int nt = h ? (nt0 + NTLO) : nt0;
        const int c = nt * 8 + 2 * t;
        if (ok0) {
            if (c < NKOUT)     o0[c]     = acc[nt0][0];
            if (c + 1 < NKOUT) o0[c + 1] = acc[nt0][1];
        }
        if (ok1) {
            if (c < NKOUT)     o1[c]     = acc[nt0][2];
            if (c + 1 < NKOUT) o1[c + 1] = acc[nt0][3];
        }
    }
}

extern "C" void kernel_launch(void* const* d_in, const int* in_sizes, int n_in,
                              void* d_out, int out_size) {
    const float* in1 = (const float*)d_in[0];
    const float* in2 = (const float*)d_in[1];
    const float* cb  = (const float*)d_in[2];
    float* out = (float*)d_out;

    const int B = in_sizes[0] / 9;
    const int grid = (B + ROWS - 1) / ROWS;
    const size_t smem_bytes = SMEM_FLOATS * sizeof(float);   // 40,256 B

    cudaFuncSetAttribute(tp_mma, cudaFuncAttributeMaxDynamicSharedMemorySize,
                         (int)smem_bytes);

    prep_kernel<<<1, 128>>>(cb);
    tp_mma<<<grid, TPB, smem_bytes>>>(in1, in2, out, B);
}